// round 2
// baseline (speedup 1.0000x reference)
#include <cuda_runtime.h>
#include <cuda_fp16.h>
#include <mma.h>
#include <math.h>

using namespace nvcuda;

#define S_LEN 2048
#define HID   4096
#define NHEAD 32
#define HDIM  64   /* half head dim used in rope indexing */
#define INTER 11008

// ---------------- scratch buffers (device globals, no runtime alloc) ----------------
__device__ __half g_Wq[HID * HID];
__device__ __half g_Wk[HID * HID];
__device__ __half g_Wv[HID * HID];
__device__ __half g_Wo[HID * HID];
__device__ __half g_Wg[INTER * HID];
__device__ __half g_Wu[INTER * HID];
__device__ __half g_Wd[HID * INTER];

__device__ __half g_Xn [S_LEN * HID];
__device__ float  g_Qf [S_LEN * HID];
__device__ float  g_Kf [S_LEN * HID];
__device__ float  g_Vf [S_LEN * HID];
__device__ __half g_Qh [S_LEN * HID];
__device__ __half g_Kh [S_LEN * HID];
__device__ __half g_Vh [S_LEN * HID];

__device__ float  g_Scores[134217728];  // 32 * 2048 * 2048 fp32 = 512MB
__device__ __half g_Probs [134217728];  // 256MB

__device__ float  g_AttnF[S_LEN * HID];
__device__ __half g_AttnH[S_LEN * HID];
__device__ float  g_H1   [S_LEN * HID];
__device__ __half g_Xn2  [S_LEN * HID];

__device__ float  g_Gf[S_LEN * INTER];
__device__ float  g_Uf[S_LEN * INTER];
__device__ __half g_Mh[S_LEN * INTER];

// ---------------- elementwise kernels ----------------
__global__ void f2h_kernel(const float* __restrict__ in, __half* __restrict__ out, long long n) {
    long long i = ((long long)blockIdx.x * blockDim.x + threadIdx.x) * 4;
    long long stride = (long long)gridDim.x * blockDim.x * 4;
    for (; i < n; i += stride) {
        float4 v = *(const float4*)(in + i);
        *(__half2*)(out + i)     = __floats2half2_rn(v.x, v.y);
        *(__half2*)(out + i + 2) = __floats2half2_rn(v.z, v.w);
    }
}

__global__ void add_kernel(float* __restrict__ a, const float* __restrict__ b, long long n) {
    long long i = ((long long)blockIdx.x * blockDim.x + threadIdx.x) * 4;
    long long stride = (long long)gridDim.x * blockDim.x * 4;
    for (; i < n; i += stride) {
        float4 va = *(const float4*)(a + i);
        float4 vb = *(const float4*)(b + i);
        va.x += vb.x; va.y += vb.y; va.z += vb.z; va.w += vb.w;
        *(float4*)(a + i) = va;
    }
}

__global__ void rmsnorm_kernel(const float* __restrict__ x, const float* __restrict__ w,
                               __half* __restrict__ out) {
    int row = blockIdx.x;
    const float* xr = x + (long long)row * HID;
    float ss = 0.f;
    for (int c = threadIdx.x * 4; c < HID; c += blockDim.x * 4) {
        float4 v = *(const float4*)(xr + c);
        ss += v.x * v.x + v.y * v.y + v.z * v.z + v.w * v.w;
    }
#pragma unroll
    for (int o = 16; o > 0; o >>= 1) ss += __shfl_xor_sync(0xffffffffu, ss, o);
    __shared__ float sh[8];
    __shared__ float inv_s;
    if ((threadIdx.x & 31) == 0) sh[threadIdx.x >> 5] = ss;
    __syncthreads();
    if (threadIdx.x == 0) {
        float t = 0.f;
        for (int i = 0; i < 8; i++) t += sh[i];
        inv_s = rsqrtf(t / (float)HID + 1e-5f);
    }
    __syncthreads();
    float inv = inv_s;
    __half* orow = out + (long long)row * HID;
    for (int c = threadIdx.x * 4; c < HID; c += blockDim.x * 4) {
        float4 v  = *(const float4*)(xr + c);
        float4 wv = *(const float4*)(w + c);
        *(__half2*)(orow + c)     = __floats2half2_rn(v.x * inv * wv.x, v.y * inv * wv.y);
        *(__half2*)(orow + c + 2) = __floats2half2_rn(v.z * inv * wv.z, v.w * inv * wv.w);
    }
}

__global__ void rope_kernel(const float* __restrict__ Qf, const float* __restrict__ Kf,
                            const int* __restrict__ pos,
                            __half* __restrict__ Qh, __half* __restrict__ Kh) {
    int t = blockIdx.x * blockDim.x + threadIdx.x;
    if (t >= S_LEN * 2048) return;
    int s = t >> 11;
    int r = t & 2047;
    int h = r >> 6;
    int j = r & 63;
    float p = (float)pos[s];
    float invf = powf(10000.0f, -(float)j / 64.0f);
    float ang = p * invf;
    float c, sn;
    sincosf(ang, &sn, &c);
    long long base = (long long)s * HID + h * 128 + j;
    float q1 = Qf[base], q2 = Qf[base + 64];
    Qh[base]      = __float2half(q1 * c - q2 * sn);
    Qh[base + 64] = __float2half(q2 * c + q1 * sn);
    float k1 = Kf[base], k2 = Kf[base + 64];
    Kh[base]      = __float2half(k1 * c - k2 * sn);
    Kh[base + 64] = __float2half(k2 * c + k1 * sn);
}

__global__ void softmax_kernel(const float* __restrict__ Sc, __half* __restrict__ Pr) {
    int i = blockIdx.x, h = blockIdx.y;
    const float* srow = Sc + ((long long)h * S_LEN + i) * S_LEN;
    __half* prow      = Pr + ((long long)h * S_LEN + i) * S_LEN;
    int len = i + 1;
    float mx = -3.4e38f;
    for (int j = threadIdx.x; j < len; j += blockDim.x) mx = fmaxf(mx, srow[j]);
#pragma unroll
    for (int o = 16; o > 0; o >>= 1) mx = fmaxf(mx, __shfl_xor_sync(0xffffffffu, mx, o));
    __shared__ float sh[8];
    __shared__ float bmx, bsum;
    if ((threadIdx.x & 31) == 0) sh[threadIdx.x >> 5] = mx;
    __syncthreads();
    if (threadIdx.x == 0) {
        float t = -3.4e38f;
        for (int a = 0; a < 8; a++) t = fmaxf(t, sh[a]);
        bmx = t;
    }
    __syncthreads();
    mx = bmx;
    float sum = 0.f;
    for (int j = threadIdx.x; j < len; j += blockDim.x) sum += expf(srow[j] - mx);
#pragma unroll
    for (int o = 16; o > 0; o >>= 1) sum += __shfl_xor_sync(0xffffffffu, sum, o);
    if ((threadIdx.x & 31) == 0) sh[threadIdx.x >> 5] = sum;
    __syncthreads();
    if (threadIdx.x == 0) {
        float t = 0.f;
        for (int a = 0; a < 8; a++) t += sh[a];
        bsum = t;
    }
    __syncthreads();
    float inv = 1.f / bsum;
    for (int j = threadIdx.x; j < S_LEN; j += blockDim.x) {
        float pv = (j < len) ? expf(srow[j] - mx) * inv : 0.f;
        prow[j] = __float2half(pv);
    }
}

__global__ void silu_kernel(const float* __restrict__ g, const float* __restrict__ u,
                            __half* __restrict__ out, long long n) {
    long long i = ((long long)blockIdx.x * blockDim.x + threadIdx.x) * 4;
    long long stride = (long long)gridDim.x * blockDim.x * 4;
    for (; i < n; i += stride) {
        float4 gv = *(const float4*)(g + i);
        float4 uv = *(const float4*)(u + i);
        float m0 = gv.x / (1.f + expf(-gv.x)) * uv.x;
        float m1 = gv.y / (1.f + expf(-gv.y)) * uv.y;
        float m2 = gv.z / (1.f + expf(-gv.z)) * uv.z;
        float m3 = gv.w / (1.f + expf(-gv.w)) * uv.w;
        *(__half2*)(out + i)     = __floats2half2_rn(m0, m1);
        *(__half2*)(out + i + 2) = __floats2half2_rn(m2, m3);
    }
}

// ---------------- generic wmma GEMM ----------------
// C[M,N] = alpha * A[M,K] * op(B)
//   B_ROW=false: B is [N,K] row-major (K contiguous)  -> matrix_b col_major
//   B_ROW=true : B is [K,N] row-major (N contiguous)  -> matrix_b row_major
//   CSKIP:  skip tiles strictly above the diagonal (scores, causal)
//   KCAUSAL: limit K loop to m0+BM (P*V with causal probs zero beyond)
#define BMT 128
#define BNT 128
#define BKT 32
#define PADA 8

template <bool B_ROW, bool CSKIP, bool KCAUSAL>
__global__ __launch_bounds__(256) void gemm_tc(
    const __half* __restrict__ Ag, const __half* __restrict__ Bg, float* __restrict__ Cg,
    int M, int N, int K, int lda, int ldb, int ldc,
    long long offA, long long offB, long long offC, float alpha) {
    int bn = blockIdx.x, bm = blockIdx.y, bz = blockIdx.z;
    int m0 = bm * BMT, n0 = bn * BNT;
    if (CSKIP && n0 > m0) return;
    const __half* A = Ag + (long long)bz * offA;
    const __half* B = Bg + (long long)bz * offB;
    float* C = Cg + (long long)bz * offC;
    int Keff = KCAUSAL ? min(K, m0 + BMT) : K;
    int nk = Keff / BKT;

    __shared__ __half As[2][BMT * (BKT + PADA)];
    __shared__ __half Bs[2][BMT * (BKT + PADA)];

    int tid = threadIdx.x;
    int warp = tid >> 5;
    int wm = warp & 3, wn = warp >> 2;

    int arow = tid >> 2;        // 0..63 (two passes of 64 rows)
    int acol = (tid & 3) * 8;   // 0,8,16,24
    int brow_r = tid >> 4;      // 0..15 (two passes of 16 rows)
    int bcol_r = (tid & 15) * 8;

    int4 ra[2], rb[2];

    // prologue: load tile 0
    {
        int k0 = 0;
#pragma unroll
        for (int p = 0; p < 2; p++)
            ra[p] = *(const int4*)(A + (long long)(m0 + arow + p * 64) * lda + k0 + acol);
        if (B_ROW) {
#pragma unroll
            for (int p = 0; p < 2; p++)
                rb[p] = *(const int4*)(B + (long long)(k0 + brow_r + p * 16) * ldb + n0 + bcol_r);
        } else {
#pragma unroll
            for (int p = 0; p < 2; p++)
                rb[p] = *(const int4*)(B + (long long)(n0 + arow + p * 64) * ldb + k0 + acol);
        }
#pragma unroll
        for (int p = 0; p < 2; p++)
            *(int4*)(&As[0][(arow + p * 64) * (BKT + PADA) + acol]) = ra[p];
        if (B_ROW) {
#pragma unroll
            for (int p = 0; p < 2; p++)
                *(int4*)(&Bs[0][(brow_r + p * 16) * (BNT + PADA) + bcol_r]) = rb[p];
        } else {
#pragma unroll
            for (int p = 0; p < 2; p++)
                *(int4*)(&Bs[0][(arow + p * 64) * (BKT + PADA) + acol]) = rb[p];
        }
    }
    __syncthreads();

    wmma::fragment<wmma::accumulator, 16, 16, 16, float> cf[2][4];
#pragma unroll
    for (int i = 0; i < 2; i++)
#pragma unroll
        for (int j = 0; j < 4; j++) wmma::fill_fragment(cf[i][j], 0.f);

    for (int kt = 0; kt < nk; kt++) {
        int buf = kt & 1;
        bool has_next = (kt + 1 < nk);
        if (has_next) {
            int k0 = (kt + 1) * BKT;
#pragma unroll
            for (int p = 0; p < 2; p++)
                ra[p] = *(const int4*)(A + (long long)(m0 + arow + p * 64) * lda + k0 + acol);
            if (B_ROW) {
#pragma unroll
                for (int p = 0; p < 2; p++)
                    rb[p] = *(const int4*)(B + (long long)(k0 + brow_r + p * 16) * ldb + n0 + bcol_r);
            } else {
#pragma unroll
                for (int p = 0; p < 2; p++)
                    rb[p] = *(const int4*)(B + (long long)(n0 + arow + p * 64) * ldb + k0 + acol);
            }
        }
#pragma unroll
        for (int kk = 0; kk < 2; kk++) {
            wmma::fragment<wmma::matrix_a, 16, 16, 16, __half, wmma::row_major> af[2];
#pragma unroll
            for (int i = 0; i < 2; i++)
                wmma::load_matrix_sync(af[i], &As[buf][(wm * 32 + i * 16) * (BKT + PADA) + kk * 16], BKT + PADA);
            if (B_ROW) {
                wmma::fragment<wmma::matrix_b, 16, 16, 16, __half, wmma::row_major> bf[4];
#pragma unroll
                for (int j = 0; j < 4; j++)
                    wmma::load_matrix_sync(bf[j], &Bs[buf][(kk * 16) * (BNT + PADA) + wn * 64 + j * 16], BNT + PADA);
#pragma unroll
                for (int i = 0; i < 2; i++)
#pragma unroll
                    for (int j = 0; j < 4; j++) wmma::mma_sync(cf[i][j], af[i], bf[j], cf[i][j]);
            } else {
                wmma::fragment<wmma::matrix_b, 16, 16, 16, __half, wmma::col_major> bf[4];
#pragma unroll
                for (int j = 0; j < 4; j++)
                    wmma::load_matrix_sync(bf[j], &Bs[buf][(wn * 64 + j * 16) * (BKT + PADA) + kk * 16], BKT + PADA);
#pragma unroll
                for (int i = 0; i < 2; i++)
#pragma unroll
                    for (int j = 0; j < 4; j++) wmma::mma_sync(cf[i][j], af[i], bf[j], cf[i][j]);
            }
        }
        if (has_next) {
            int nb = 1 - buf;
#pragma unroll
            for (int p = 0; p < 2; p++)
                *(int4*)(&As[nb][(arow + p * 64) * (BKT + PADA) + acol]) = ra[p];
            if (B_ROW) {
#pragma unroll
                for (int p = 0; p < 2; p++)
                    *(int4*)(&Bs[nb][(brow_r + p * 16) * (BNT + PADA) + bcol_r]) = rb[p];
            } else {
#pragma unroll
                for (int p = 0; p < 2; p++)
                    *(int4*)(&Bs[nb][(arow + p * 64) * (BKT + PADA) + acol]) = rb[p];
            }
            __syncthreads();
        }
    }

#pragma unroll
    for (int i = 0; i < 2; i++)
#pragma unroll
        for (int j = 0; j < 4; j++) {
#pragma unroll
            for (int e = 0; e < cf[i][j].num_elements; e++) cf[i][j].x[e] *= alpha;
            wmma::store_matrix_sync(C + (long long)(m0 + wm * 32 + i * 16) * ldc + n0 + wn * 64 + j * 16,
                                    cf[i][j], ldc, wmma::mem_row_major);
        }
}

// ---------------- host orchestration ----------------
extern "C" void kernel_launch(void* const* d_in, const int* in_sizes, int n_in,
                              void* d_out, int out_size) {
    const float* hidden = (const float*)d_in[0];
    const int*   pos    = (const int*)d_in[1];
    const float* ln1    = (const float*)d_in[2];
    const float* ln2    = (const float*)d_in[3];
    const float* wq     = (const float*)d_in[4];
    const float* wk     = (const float*)d_in[5];
    const float* wv     = (const float*)d_in[6];
    const float* wo     = (const float*)d_in[7];
    const float* wg     = (const float*)d_in[8];
    const float* wu     = (const float*)d_in[9];
    const float* wd     = (const float*)d_in[10];
    float* out = (float*)d_out;

    void *pWq, *pWk, *pWv, *pWo, *pWg, *pWu, *pWd;
    void *pXn, *pQf, *pKf, *pVf, *pQh, *pKh, *pVh;
    void *pSc, *pPr, *pAf, *pAh, *pH1, *pXn2, *pGf, *pUf, *pMh;
    cudaGetSymbolAddress(&pWq, g_Wq);   cudaGetSymbolAddress(&pWk, g_Wk);
    cudaGetSymbolAddress(&pWv, g_Wv);   cudaGetSymbolAddress(&pWo, g_Wo);
    cudaGetSymbolAddress(&pWg, g_Wg);   cudaGetSymbolAddress(&pWu, g_Wu);
    cudaGetSymbolAddress(&pWd, g_Wd);
    cudaGetSymbolAddress(&pXn, g_Xn);   cudaGetSymbolAddress(&pQf, g_Qf);
    cudaGetSymbolAddress(&pKf, g_Kf);   cudaGetSymbolAddress(&pVf, g_Vf);
    cudaGetSymbolAddress(&pQh, g_Qh);   cudaGetSymbolAddress(&pKh, g_Kh);
    cudaGetSymbolAddress(&pVh, g_Vh);
    cudaGetSymbolAddress(&pSc, g_Scores); cudaGetSymbolAddress(&pPr, g_Probs);
    cudaGetSymbolAddress(&pAf, g_AttnF);  cudaGetSymbolAddress(&pAh, g_AttnH);
    cudaGetSymbolAddress(&pH1, g_H1);     cudaGetSymbolAddress(&pXn2, g_Xn2);
    cudaGetSymbolAddress(&pGf, g_Gf);     cudaGetSymbolAddress(&pUf, g_Uf);
    cudaGetSymbolAddress(&pMh, g_Mh);

    const long long nHH = (long long)HID * HID;
    const long long nIH = (long long)INTER * HID;
    const long long nSH = (long long)S_LEN * HID;
    const long long nSI = (long long)S_LEN * INTER;
    const float inv_sqrt_d = 0.08838834764831845f;  // 1/sqrt(128)

    // 1. weights fp32 -> fp16
    f2h_kernel<<<4096, 256>>>(wq, (__half*)pWq, nHH);
    f2h_kernel<<<4096, 256>>>(wk, (__half*)pWk, nHH);
    f2h_kernel<<<4096, 256>>>(wv, (__half*)pWv, nHH);
    f2h_kernel<<<4096, 256>>>(wo, (__half*)pWo, nHH);
    f2h_kernel<<<4096, 256>>>(wg, (__half*)pWg, nIH);
    f2h_kernel<<<4096, 256>>>(wu, (__half*)pWu, nIH);
    f2h_kernel<<<4096, 256>>>(wd, (__half*)pWd, nIH);

    // 2. rmsnorm 1
    rmsnorm_kernel<<<S_LEN, 256>>>(hidden, ln1, (__half*)pXn);

    // 3. QKV projections
    gemm_tc<false, false, false><<<dim3(32, 16, 1), 256>>>(
        (const __half*)pXn, (const __half*)pWq, (float*)pQf,
        S_LEN, HID, HID, HID, HID, HID, 0, 0, 0, 1.f);
    gemm_tc<false, false, false><<<dim3(32, 16, 1), 256>>>(
        (const __half*)pXn, (const __half*)pWk, (float*)pKf,
        S_LEN, HID, HID, HID, HID, HID, 0, 0, 0, 1.f);
    gemm_tc<false, false, false><<<dim3(32, 16, 1), 256>>>(
        (const __half*)pXn, (const __half*)pWv, (float*)pVf,
        S_LEN, HID, HID, HID, HID, HID, 0, 0, 0, 1.f);

    // 4. rope (Q,K) -> fp16 ; V -> fp16
    rope_kernel<<<(S_LEN * 2048 + 255) / 256, 256>>>(
        (const float*)pQf, (const float*)pKf, pos, (__half*)pQh, (__half*)pKh);
    f2h_kernel<<<4096, 256>>>((const float*)pVf, (__half*)pVh, nSH);

    // 5. scores = Q K^T / sqrt(d), causal tile skip, per head
    gemm_tc<false, true, false><<<dim3(16, 16, NHEAD), 256>>>(
        (const __half*)pQh, (const __half*)pKh, (float*)pSc,
        S_LEN, S_LEN, 128, HID, HID, S_LEN,
        128, 128, (long long)S_LEN * S_LEN, inv_sqrt_d);

    // 6. causal softmax -> fp16 probs
    softmax_kernel<<<dim3(S_LEN, NHEAD), 256>>>((const float*)pSc, (__half*)pPr);

    // 7. attn = P V, causal K-limit, per head
    gemm_tc<true, false, true><<<dim3(1, 16, NHEAD), 256>>>(
        (const __half*)pPr, (const __half*)pVh, (float*)pAf,
        S_LEN, 128, S_LEN, S_LEN, HID, HID,
        (long long)S_LEN * S_LEN, 128, 128, 1.f);

    // 8. O projection + residual
    f2h_kernel<<<4096, 256>>>((const float*)pAf, (__half*)pAh, nSH);
    gemm_tc<false, false, false><<<dim3(32, 16, 1), 256>>>(
        (const __half*)pAh, (const __half*)pWo, (float*)pH1,
        S_LEN, HID, HID, HID, HID, HID, 0, 0, 0, 1.f);
    add_kernel<<<4096, 256>>>((float*)pH1, hidden, nSH);

    // 9. MLP
    rmsnorm_kernel<<<S_LEN, 256>>>((const float*)pH1, ln2, (__half*)pXn2);
    gemm_tc<false, false, false><<<dim3(86, 16, 1), 256>>>(
        (const __half*)pXn2, (const __half*)pWg, (float*)pGf,
        S_LEN, INTER, HID, HID, HID, INTER, 0, 0, 0, 1.f);
    gemm_tc<false, false, false><<<dim3(86, 16, 1), 256>>>(
        (const __half*)pXn2, (const __half*)pWu, (float*)pUf,
        S_LEN, INTER, HID, HID, HID, INTER, 0, 0, 0, 1.f);
    silu_kernel<<<4096, 256>>>((const float*)pGf, (const float*)pUf, (__half*)pMh, nSI);
    gemm_tc<false, false, false><<<dim3(32, 16, 1), 256>>>(
        (const __half*)pMh, (const __half*)pWd, out,
        S_LEN, HID, INTER, INTER, INTER, HID, 0, 0, 0, 1.f);
    add_kernel<<<4096, 256>>>(out, (const float*)pH1, nSH);
}